// round 16
// baseline (speedup 1.0000x reference)
#include <cuda_runtime.h>
#include <math.h>

#define NN 40000
#define EE 640000
#define GG 32
#define HH 128
#define LL 4
#define OO 100

// ---------------- device scratch ----------------
__device__ float g_hA[NN * HH];
__device__ float g_hB[NN * HH];
__device__ float g_q [NN * HH];
__device__ float g_k [NN * HH];
__device__ float g_v [NN * HH];
__device__ float g_s [NN * HH];
__device__ float g_eap[EE * 8];        // raw edge_attr, CSR-permuted, padded to 8
__device__ float g_Y  [LL * 4 * 5 * 32];
__device__ float g_yb [LL * 4 * 32];
__device__ float g_Z2 [LL * 5 * 128];
__device__ float g_zb2[LL * 128];
__device__ int   g_hist[NN];
__device__ int   g_rowstart[NN + 1];
__device__ int   g_cursor[NN];
__device__ int   g_edgepos[EE];
__device__ int   g_csrsrc[EE];
__device__ float g_pool[GG * HH];
__device__ float g_pcnt[GG];

// ---------------- CSR construction ----------------
__global__ void k_zero()
{
    int i = blockIdx.x * blockDim.x + threadIdx.x;
    if (i < NN) g_hist[i] = 0;
    if (i < GG * HH) g_pool[i] = 0.f;
    if (i < GG) g_pcnt[i] = 0.f;
}

__global__ void k_hist(const int* __restrict__ ei)
{
    int e = blockIdx.x * blockDim.x + threadIdx.x;
    if (e < EE) atomicAdd(&g_hist[ei[EE + e]], 1);
}

__global__ void k_scan()
{
    const int T = 1024, CH = 40;
    __shared__ int sh[T];
    int t = threadIdx.x;
    int base = t * CH;
    int loc[CH];
    int run = 0;
#pragma unroll
    for (int i = 0; i < CH; i++) {
        int idx = base + i;
        int vv = (idx < NN) ? g_hist[idx] : 0;
        loc[i] = run;
        run += vv;
    }
    sh[t] = run;
    __syncthreads();
    for (int off = 1; off < T; off <<= 1) {
        int vv = (t >= off) ? sh[t - off] : 0;
        __syncthreads();
        sh[t] += vv;
        __syncthreads();
    }
    int offset = (t > 0) ? sh[t - 1] : 0;
#pragma unroll
    for (int i = 0; i < CH; i++) {
        int idx = base + i;
        if (idx < NN) {
            int p = offset + loc[i];
            g_rowstart[idx] = p;
            g_cursor[idx]   = p;
        }
    }
    if (t == T - 1) g_rowstart[NN] = sh[T - 1];
}

__global__ void k_scatter(const int* __restrict__ ei)
{
    int e = blockIdx.x * blockDim.x + threadIdx.x;
    if (e < EE) {
        int dst = ei[EE + e];
        int pos = atomicAdd(&g_cursor[dst], 1);
        g_edgepos[e] = pos;
        g_csrsrc[pos] = ei[e];
    }
}

__global__ void k_permea(const float* __restrict__ ea)
{
    int e = blockIdx.x * blockDim.x + threadIdx.x;
    if (e >= EE) return;
    int pos = g_edgepos[e];
    float* dst = g_eap + (size_t)pos * 8;
    const float* src = ea + (size_t)e * 5;
    dst[0] = src[0]; dst[1] = src[1]; dst[2] = src[2];
    dst[3] = src[3]; dst[4] = src[4];
    dst[5] = 0.f; dst[6] = 0.f; dst[7] = 0.f;
}

// ---------------- input projection ----------------
__global__ void k_nodeproj(const float* __restrict__ x,
                           const float* __restrict__ w,
                           const float* __restrict__ b)
{
    int t = blockIdx.x * blockDim.x + threadIdx.x;
    if (t >= NN * HH) return;
    int n = t >> 7, c = t & 127;
    const float* xr = x + n * 4;
    float acc = b[c];
    acc += xr[0] * w[c] + xr[1] * w[128 + c] + xr[2] * w[256 + c] + xr[3] * w[384 + c];
    g_hA[t] = acc;
}

// ---------------- weight precompute: Y (scaled), yb (scaled), Z2, zb2 ----------------
__global__ void k_prep(const float* __restrict__ We,
                       const float* __restrict__ edge_w,
                       const float* __restrict__ edge_b)
{
    const float scale = 0.17677669529663687f;
    int t = blockIdx.x * blockDim.x + threadIdx.x;
    if (t < 2560) {                       // Y[l][h][m][c]
        int l = t / 640, r = t % 640;
        int h = r / 160, r2 = r % 160;
        int m = r2 / 32, c = r2 % 32;
        float acc = 0.f;
        for (int j = 0; j < 128; j++)
            acc += edge_w[m * 128 + j] * We[l * 16384 + j * 128 + h * 32 + c];
        g_Y[t] = acc * scale;
    } else if (t < 3072) {                // yb[l][h][c]
        int i = t - 2560;
        int l = i / 128, h = (i % 128) / 32, c = i % 32;
        float acc = 0.f;
        for (int j = 0; j < 128; j++)
            acc += edge_b[j] * We[l * 16384 + j * 128 + h * 32 + c];
        g_yb[i] = acc * scale;
    } else if (t < 5632) {                // Z2[l][m][col]
        int i = t - 3072;
        int l = i / 640, m = (i % 640) / 128, col = i % 128;
        float acc = 0.f;
        for (int j = 0; j < 128; j++)
            acc += edge_w[m * 128 + j] * We[l * 16384 + j * 128 + col];
        g_Z2[i] = acc;
    } else if (t < 6144) {                // zb2[l][col]
        int i = t - 5632;
        int l = i / 128, col = i % 128;
        float acc = 0.f;
        for (int j = 0; j < 128; j++)
            acc += edge_b[j] * We[l * 16384 + j * 128 + col];
        g_zb2[i] = acc;
    }
}

// ---------------- fused 4-matrix GEMM (proven scalar version) ----------------
#define BM 64
#define BK 16

__global__ void gemm4(const float* __restrict__ A,
                      const float* __restrict__ B0, const float* __restrict__ B1,
                      const float* __restrict__ B2, const float* __restrict__ B3,
                      const float* __restrict__ c0, const float* __restrict__ c1,
                      const float* __restrict__ c2, const float* __restrict__ c3,
                      float* __restrict__ C0, float* __restrict__ C1,
                      float* __restrict__ C2, float* __restrict__ C3)
{
    const float* B    = (blockIdx.y == 0) ? B0 : (blockIdx.y == 1) ? B1 : (blockIdx.y == 2) ? B2 : B3;
    const float* bias = (blockIdx.y == 0) ? c0 : (blockIdx.y == 1) ? c1 : (blockIdx.y == 2) ? c2 : c3;
    float* C          = (blockIdx.y == 0) ? C0 : (blockIdx.y == 1) ? C1 : (blockIdx.y == 2) ? C2 : C3;

    __shared__ float As[BK][BM + 4];
    __shared__ float Bs[BK][128];
    int tid  = threadIdx.x;
    int tcol = tid & 15;
    int trow = tid >> 4;
    int block_m = blockIdx.x * BM;

    float acc[8][8];
#pragma unroll
    for (int i = 0; i < 8; i++)
#pragma unroll
        for (int j = 0; j < 8; j++) acc[i][j] = 0.f;

    for (int k0 = 0; k0 < 128; k0 += BK) {
#pragma unroll
        for (int it = 0; it < 2; it++) {
            int f = tid + it * 128;
            int row = f >> 2;
            int kq  = f & 3;
            float4 a = *(const float4*)&A[(size_t)(block_m + row) * 128 + k0 + kq * 4];
            As[kq * 4 + 0][row] = a.x;
            As[kq * 4 + 1][row] = a.y;
            As[kq * 4 + 2][row] = a.z;
            As[kq * 4 + 3][row] = a.w;
        }
#pragma unroll
        for (int it = 0; it < 4; it++) {
            int f = tid + it * 128;
            int krow = f >> 5;
            int nq   = f & 31;
            *(float4*)&Bs[krow][nq * 4] = *(const float4*)&B[(k0 + krow) * 128 + nq * 4];
        }
        __syncthreads();
#pragma unroll
        for (int k = 0; k < BK; k++) {
            float a[8], b[8];
            *(float4*)&a[0] = *(float4*)&As[k][trow * 4];
            *(float4*)&a[4] = *(float4*)&As[k][32 + trow * 4];
            *(float4*)&b[0] = *(float4*)&Bs[k][tcol * 4];
            *(float4*)&b[4] = *(float4*)&Bs[k][64 + tcol * 4];
#pragma unroll
            for (int i = 0; i < 8; i++)
#pragma unroll
                for (int j = 0; j < 8; j++)
                    acc[i][j] += a[i] * b[j];
        }
        __syncthreads();
    }

    float4 bLo = *(const float4*)&bias[tcol * 4];
    float4 bHi = *(const float4*)&bias[64 + tcol * 4];
#pragma unroll
    for (int i = 0; i < 8; i++) {
        int row = block_m + ((i < 4) ? (trow * 4 + i) : (32 + trow * 4 + i - 4));
        float4 lo, hi;
        lo.x = acc[i][0] + bLo.x; lo.y = acc[i][1] + bLo.y;
        lo.z = acc[i][2] + bLo.z; lo.w = acc[i][3] + bLo.w;
        hi.x = acc[i][4] + bHi.x; hi.y = acc[i][5] + bHi.y;
        hi.z = acc[i][6] + bHi.z; hi.w = acc[i][7] + bHi.w;
        *(float4*)&C[(size_t)row * 128 + tcol * 4]      = lo;
        *(float4*)&C[(size_t)row * 128 + 64 + tcol * 4] = hi;
    }
}

// ---------------- attention v9: fully fused (z prologue + edges + og + LN + ReLU) --------
__global__ void k_attn6(const float* __restrict__ q, const float* __restrict__ kk,
                        const float* __restrict__ vv, const float* __restrict__ sk,
                        const float* __restrict__ lng, const float* __restrict__ lnb,
                        int l, float* __restrict__ hout)
{
    int wrp  = (blockIdx.x * blockDim.x + threadIdx.x) >> 5;
    int lane = threadIdx.x & 31;
    if (wrp >= NN) return;
    int g  = lane >> 3;
    int l8 = lane & 7;
    const float scale = 0.17677669529663687f;
    const unsigned FULL = 0xffffffffu;

    // raw q chunk for own head
    float4 qr = *(const float4*)(q + (size_t)wrp * 128 + g * 32 + l8 * 4);

    // ---- z prologue ----
    const float* Yh  = g_Y  + (size_t)(l * 4 + g) * 160 + l8 * 4;
    const float* ybh = g_yb + (size_t)(l * 4 + g) * 32  + l8 * 4;
    float4 y0 = *(const float4*)(Yh +   0);
    float4 y1 = *(const float4*)(Yh +  32);
    float4 y2 = *(const float4*)(Yh +  64);
    float4 y3 = *(const float4*)(Yh +  96);
    float4 y4 = *(const float4*)(Yh + 128);
    float4 yB = *(const float4*)(ybh);
    float z0 = qr.x * y0.x + qr.y * y0.y + qr.z * y0.z + qr.w * y0.w;
    float z1 = qr.x * y1.x + qr.y * y1.y + qr.z * y1.z + qr.w * y1.w;
    float z2 = qr.x * y2.x + qr.y * y2.y + qr.z * y2.z + qr.w * y2.w;
    float z3 = qr.x * y3.x + qr.y * y3.y + qr.z * y3.z + qr.w * y3.w;
    float z4 = qr.x * y4.x + qr.y * y4.y + qr.z * y4.z + qr.w * y4.w;
    float zb = qr.x * yB.x + qr.y * yB.y + qr.z * yB.z + qr.w * yB.w;
#pragma unroll
    for (int off = 1; off < 8; off <<= 1) {
        z0 += __shfl_xor_sync(FULL, z0, off);
        z1 += __shfl_xor_sync(FULL, z1, off);
        z2 += __shfl_xor_sync(FULL, z2, off);
        z3 += __shfl_xor_sync(FULL, z3, off);
        z4 += __shfl_xor_sync(FULL, z4, off);
        zb += __shfl_xor_sync(FULL, zb, off);
    }

    float4 q4;
    q4.x = qr.x * scale; q4.y = qr.y * scale;
    q4.z = qr.z * scale; q4.w = qr.w * scale;

    float ssum = 0.f;
    float ag0 = 0.f, ag1 = 0.f, ag2 = 0.f, ag3 = 0.f, ag4 = 0.f;
    float4 vacc = make_float4(0.f, 0.f, 0.f, 0.f);

    int beg = g_rowstart[wrp], end = g_rowstart[wrp + 1];
    int idx = beg;

    for (; idx + 1 < end; idx += 2) {
        int sA = g_csrsrc[idx];
        int sB = g_csrsrc[idx + 1];
        float4 eaA  = *(const float4*)(g_eap + (size_t)idx * 8);
        float  eaA4 = g_eap[(size_t)idx * 8 + 4];
        float4 eaB  = *(const float4*)(g_eap + (size_t)(idx + 1) * 8);
        float  eaB4 = g_eap[(size_t)(idx + 1) * 8 + 4];
        float4 kA = *(const float4*)(kk + (size_t)sA * 128 + g * 32 + l8 * 4);
        float4 kB = *(const float4*)(kk + (size_t)sB * 128 + g * 32 + l8 * 4);
        float4 vA = *(const float4*)(vv + (size_t)sA * 128 + g * 32 + l8 * 4);
        float4 vB = *(const float4*)(vv + (size_t)sB * 128 + g * 32 + l8 * 4);

        float pA = q4.x * kA.x + q4.y * kA.y + q4.z * kA.z + q4.w * kA.w;
        float pB = q4.x * kB.x + q4.y * kB.y + q4.z * kB.z + q4.w * kB.w;
        pA += __shfl_xor_sync(FULL, pA, 1);  pB += __shfl_xor_sync(FULL, pB, 1);
        pA += __shfl_xor_sync(FULL, pA, 2);  pB += __shfl_xor_sync(FULL, pB, 2);
        pA += __shfl_xor_sync(FULL, pA, 4);  pB += __shfl_xor_sync(FULL, pB, 4);

        float dA = zb + eaA.x * z0 + eaA.y * z1 + eaA.z * z2 + eaA.w * z3 + eaA4 * z4;
        float dB = zb + eaB.x * z0 + eaB.y * z1 + eaB.z * z2 + eaB.w * z3 + eaB4 * z4;

        float wA = __expf(pA + dA);
        float wB = __expf(pB + dB);
        ssum += wA + wB;

        ag0 += wA * eaA.x + wB * eaB.x;
        ag1 += wA * eaA.y + wB * eaB.y;
        ag2 += wA * eaA.z + wB * eaB.z;
        ag3 += wA * eaA.w + wB * eaB.w;
        ag4 += wA * eaA4  + wB * eaB4;

        vacc.x += wA * vA.x + wB * vB.x;
        vacc.y += wA * vA.y + wB * vB.y;
        vacc.z += wA * vA.z + wB * vB.z;
        vacc.w += wA * vA.w + wB * vB.w;
    }

    if (idx < end) {
        int sA = g_csrsrc[idx];
        float4 eaA  = *(const float4*)(g_eap + (size_t)idx * 8);
        float  eaA4 = g_eap[(size_t)idx * 8 + 4];
        float4 kA = *(const float4*)(kk + (size_t)sA * 128 + g * 32 + l8 * 4);
        float4 vA = *(const float4*)(vv + (size_t)sA * 128 + g * 32 + l8 * 4);

        float pA = q4.x * kA.x + q4.y * kA.y + q4.z * kA.z + q4.w * kA.w;
        pA += __shfl_xor_sync(FULL, pA, 1);
        pA += __shfl_xor_sync(FULL, pA, 2);
        pA += __shfl_xor_sync(FULL, pA, 4);

        float dA = zb + eaA.x * z0 + eaA.y * z1 + eaA.z * z2 + eaA.w * z3 + eaA4 * z4;
        float wA = __expf(pA + dA);
        ssum += wA;
        ag0 += wA * eaA.x; ag1 += wA * eaA.y; ag2 += wA * eaA.z;
        ag3 += wA * eaA.w; ag4 += wA * eaA4;
        vacc.x += wA * vA.x; vacc.y += wA * vA.y;
        vacc.z += wA * vA.z; vacc.w += wA * vA.w;
    }

    float inv = 1.f / (ssum + 1e-16f);

    // ---- fused epilogue: tmpv + og + LN + ReLU (all in registers) ----
    // a0..a4, mass are group-uniform = exactly this head's aggregates
    float a0 = ag0 * inv, a1 = ag1 * inv, a2 = ag2 * inv;
    float a3 = ag3 * inv, a4 = ag4 * inv;
    float mass = ssum * inv;

    const float* Z2l  = g_Z2  + (size_t)l * 640;
    const float* zb2l = g_zb2 + (size_t)l * 128;
    float4 w0 = *(const float4*)&Z2l[  0 + lane * 4];
    float4 w1 = *(const float4*)&Z2l[128 + lane * 4];
    float4 w2 = *(const float4*)&Z2l[256 + lane * 4];
    float4 w3 = *(const float4*)&Z2l[384 + lane * 4];
    float4 w4 = *(const float4*)&Z2l[512 + lane * 4];
    float4 zc = *(const float4*)&zb2l[lane * 4];

    float4 s4 = *(const float4*)(sk + (size_t)wrp * 128 + lane * 4);
    float ox = vacc.x * inv + s4.x + a0 * w0.x + a1 * w1.x + a2 * w2.x + a3 * w3.x + a4 * w4.x + mass * zc.x;
    float oy = vacc.y * inv + s4.y + a0 * w0.y + a1 * w1.y + a2 * w2.y + a3 * w3.y + a4 * w4.y + mass * zc.y;
    float oz = vacc.z * inv + s4.z + a0 * w0.z + a1 * w1.z + a2 * w2.z + a3 * w3.z + a4 * w4.z + mass * zc.z;
    float ow = vacc.w * inv + s4.w + a0 * w0.w + a1 * w1.w + a2 * w2.w + a3 * w3.w + a4 * w4.w + mass * zc.w;

    float s = ox + oy + oz + ow;
#pragma unroll
    for (int off = 16; off; off >>= 1) s += __shfl_xor_sync(FULL, s, off);
    float mu = s * 0.0078125f;
    float dx = ox - mu, dy = oy - mu, dz = oz - mu, dw = ow - mu;
    float sq = dx * dx + dy * dy + dz * dz + dw * dw;
#pragma unroll
    for (int off = 16; off; off >>= 1) sq += __shfl_xor_sync(FULL, sq, off);
    float r = rsqrtf(sq * 0.0078125f + 1e-5f);

    float4 g4 = *(const float4*)&lng[lane * 4];
    float4 b4 = *(const float4*)&lnb[lane * 4];
    float4 res;
    res.x = fmaxf(0.f, dx * r * g4.x + b4.x);
    res.y = fmaxf(0.f, dy * r * g4.y + b4.y);
    res.z = fmaxf(0.f, dz * r * g4.z + b4.z);
    res.w = fmaxf(0.f, dw * r * g4.w + b4.w);
    *(float4*)(hout + (size_t)wrp * 128 + lane * 4) = res;
}

// ---------------- global mean pool + MLP heads ----------------
__global__ void k_pool(const float* __restrict__ h, const int* __restrict__ batch)
{
    int t = blockIdx.x * blockDim.x + threadIdx.x;
    if (t >= NN * HH) return;
    int n = t >> 7, c = t & 127;
    int b = batch[n];
    atomicAdd(&g_pool[b * HH + c], h[t]);
    if (c == 0) atomicAdd(&g_pcnt[b], 1.f);
}

__global__ void k_heads(const float* __restrict__ dw1, const float* __restrict__ db1,
                        const float* __restrict__ dw2, const float* __restrict__ db2,
                        const float* __restrict__ tw1, const float* __restrict__ tb1,
                        const float* __restrict__ tw2, const float* __restrict__ tb2,
                        float* __restrict__ out)
{
    const float* W1 = blockIdx.x ? tw1 : dw1;
    const float* B1 = blockIdx.x ? tb1 : db1;
    const float* W2 = blockIdx.x ? tw2 : dw2;
    const float* B2 = blockIdx.x ? tb2 : db2;

    __shared__ float hg[GG][HH];
    __shared__ float t1[GG][64];
    int t = threadIdx.x;

    for (int i = t; i < GG * HH; i += 256) {
        int g = i >> 7;
        hg[g][i & 127] = g_pool[i] / fmaxf(g_pcnt[g], 1.f);
    }
    __syncthreads();
    for (int i = t; i < GG * 64; i += 256) {
        int g = i >> 6, j = i & 63;
        float acc = B1[j];
        for (int c = 0; c < 128; c++) acc += hg[g][c] * W1[c * 64 + j];
        t1[g][j] = fmaxf(acc, 0.f);
    }
    __syncthreads();
    for (int i = t; i < GG * OO; i += 256) {
        int g = i / OO, o = i % OO;
        float acc = B2[o];
        for (int j = 0; j < 64; j++) acc += t1[g][j] * W2[j * OO + o];
        out[blockIdx.x * GG * OO + i] = acc;
    }
}

// ---------------- launch ----------------
extern "C" void kernel_launch(void* const* d_in, const int* in_sizes, int n_in,
                              void* d_out, int out_size)
{
    const float* x      = (const float*)d_in[0];
    const float* eattr  = (const float*)d_in[1];
    const float* node_w = (const float*)d_in[2];
    const float* node_b = (const float*)d_in[3];
    const float* edge_w = (const float*)d_in[4];
    const float* edge_b = (const float*)d_in[5];
    const float* Wq  = (const float*)d_in[6];
    const float* bq  = (const float*)d_in[7];
    const float* Wk  = (const float*)d_in[8];
    const float* bk  = (const float*)d_in[9];
    const float* Wv  = (const float*)d_in[10];
    const float* bv  = (const float*)d_in[11];
    const float* We  = (const float*)d_in[12];
    const float* Wsk = (const float*)d_in[13];
    const float* bsk = (const float*)d_in[14];
    const float* lng = (const float*)d_in[15];
    const float* lnb = (const float*)d_in[16];
    const float* dw1 = (const float*)d_in[17];
    const float* db1 = (const float*)d_in[18];
    const float* dw2 = (const float*)d_in[19];
    const float* db2 = (const float*)d_in[20];
    const float* tw1 = (const float*)d_in[21];
    const float* tb1 = (const float*)d_in[22];
    const float* tw2 = (const float*)d_in[23];
    const float* tb2 = (const float*)d_in[24];
    const int*   ei    = (const int*)d_in[25];
    const int*   batch = (const int*)d_in[26];
    float* out = (float*)d_out;

    float *hA, *hB, *qp, *kp, *vp, *sp;
    cudaGetSymbolAddress((void**)&hA, g_hA);
    cudaGetSymbolAddress((void**)&hB, g_hB);
    cudaGetSymbolAddress((void**)&qp, g_q);
    cudaGetSymbolAddress((void**)&kp, g_k);
    cudaGetSymbolAddress((void**)&vp, g_v);
    cudaGetSymbolAddress((void**)&sp, g_s);

    dim3 gg(NN / BM, 4);

    // gemm4 (layer 0) stays in the ncu-profiled slot (#4).
    k_zero<<<(NN + 255) / 256, 256>>>();
    k_hist<<<(EE + 255) / 256, 256>>>(ei);
    k_nodeproj<<<(NN * HH + 255) / 256, 256>>>(x, node_w, node_b);
    gemm4<<<gg, 128>>>(hA, Wq, Wk, Wv, Wsk, bq, bk, bv, bsk, qp, kp, vp, sp);
    k_scan<<<1, 1024>>>();
    k_scatter<<<(EE + 255) / 256, 256>>>(ei);
    k_permea<<<(EE + 255) / 256, 256>>>(eattr);
    k_prep<<<24, 256>>>(We, edge_w, edge_b);

    float* hcur = hA;
    float* hnxt = hB;
    for (int i = 0; i < LL; i++) {
        if (i > 0)
            gemm4<<<gg, 128>>>(hcur,
                               Wq + i * HH * HH, Wk + i * HH * HH,
                               Wv + i * HH * HH, Wsk + i * HH * HH,
                               bq + i * HH, bk + i * HH, bv + i * HH, bsk + i * HH,
                               qp, kp, vp, sp);
        k_attn6<<<(NN * 32) / 256, 256>>>(qp, kp, vp, sp,
                                          lng + i * HH, lnb + i * HH, i, hnxt);
        float* tmp = hcur; hcur = hnxt; hnxt = tmp;
    }

    k_pool<<<(NN * HH + 255) / 256, 256>>>(hcur, batch);
    k_heads<<<2, 256>>>(dw1, db1, dw2, db2, tw1, tb1, tw2, tb2, out);
}

// round 17
// speedup vs baseline: 1.0065x; 1.0065x over previous
#include <cuda_runtime.h>
#include <math.h>

#define NN 40000
#define EE 640000
#define GG 32
#define HH 128
#define LL 4
#define OO 100

// ---------------- device scratch ----------------
__device__ float g_hA[NN * HH];
__device__ float g_hB[NN * HH];
__device__ float g_q [NN * HH];
__device__ float g_k [NN * HH];
__device__ float g_v [NN * HH];
__device__ float g_s [NN * HH];
__device__ float g_eap[EE * 8];        // raw edge_attr, CSR-permuted, padded to 8
__device__ float g_Y  [LL * 4 * 5 * 32];
__device__ float g_yb [LL * 4 * 32];
__device__ float g_Z2 [LL * 5 * 128];
__device__ float g_zb2[LL * 128];
__device__ int   g_hist[NN];
__device__ int   g_rowstart[NN + 1];
__device__ int   g_cursor[NN];
__device__ int   g_edgepos[EE];
__device__ int   g_csrsrc[EE];
__device__ float g_pool[GG * HH];
__device__ float g_pcnt[GG];

// ---------------- CSR construction ----------------
__global__ void k_zero()
{
    int i = blockIdx.x * blockDim.x + threadIdx.x;
    if (i < NN) g_hist[i] = 0;
    if (i < GG * HH) g_pool[i] = 0.f;
    if (i < GG) g_pcnt[i] = 0.f;
}

__global__ void k_hist(const int* __restrict__ ei)
{
    int e = blockIdx.x * blockDim.x + threadIdx.x;
    if (e < EE) atomicAdd(&g_hist[ei[EE + e]], 1);
}

__global__ void k_scan()
{
    const int T = 1024, CH = 40;
    __shared__ int sh[T];
    int t = threadIdx.x;
    int base = t * CH;
    int loc[CH];
    int run = 0;
#pragma unroll
    for (int i = 0; i < CH; i++) {
        int idx = base + i;
        int vv = (idx < NN) ? g_hist[idx] : 0;
        loc[i] = run;
        run += vv;
    }
    sh[t] = run;
    __syncthreads();
    for (int off = 1; off < T; off <<= 1) {
        int vv = (t >= off) ? sh[t - off] : 0;
        __syncthreads();
        sh[t] += vv;
        __syncthreads();
    }
    int offset = (t > 0) ? sh[t - 1] : 0;
#pragma unroll
    for (int i = 0; i < CH; i++) {
        int idx = base + i;
        if (idx < NN) {
            int p = offset + loc[i];
            g_rowstart[idx] = p;
            g_cursor[idx]   = p;
        }
    }
    if (t == T - 1) g_rowstart[NN] = sh[T - 1];
}

__global__ void k_scatter(const int* __restrict__ ei)
{
    int e = blockIdx.x * blockDim.x + threadIdx.x;
    if (e < EE) {
        int dst = ei[EE + e];
        int pos = atomicAdd(&g_cursor[dst], 1);
        g_edgepos[e] = pos;
        g_csrsrc[pos] = ei[e];
    }
}

__global__ void k_permea(const float* __restrict__ ea)
{
    int e = blockIdx.x * blockDim.x + threadIdx.x;
    if (e >= EE) return;
    int pos = g_edgepos[e];
    float* dst = g_eap + (size_t)pos * 8;
    const float* src = ea + (size_t)e * 5;
    dst[0] = src[0]; dst[1] = src[1]; dst[2] = src[2];
    dst[3] = src[3]; dst[4] = src[4];
    dst[5] = 0.f; dst[6] = 0.f; dst[7] = 0.f;
}

// ---------------- input projection ----------------
__global__ void k_nodeproj(const float* __restrict__ x,
                           const float* __restrict__ w,
                           const float* __restrict__ b)
{
    int t = blockIdx.x * blockDim.x + threadIdx.x;
    if (t >= NN * HH) return;
    int n = t >> 7, c = t & 127;
    const float* xr = x + n * 4;
    float acc = b[c];
    acc += xr[0] * w[c] + xr[1] * w[128 + c] + xr[2] * w[256 + c] + xr[3] * w[384 + c];
    g_hA[t] = acc;
}

// ---------------- weight precompute: Y (scaled), yb (scaled), Z2, zb2 ----------------
__global__ void k_prep(const float* __restrict__ We,
                       const float* __restrict__ edge_w,
                       const float* __restrict__ edge_b)
{
    const float scale = 0.17677669529663687f;
    int t = blockIdx.x * blockDim.x + threadIdx.x;
    if (t < 2560) {                       // Y[l][h][m][c]
        int l = t / 640, r = t % 640;
        int h = r / 160, r2 = r % 160;
        int m = r2 / 32, c = r2 % 32;
        float acc = 0.f;
        for (int j = 0; j < 128; j++)
            acc += edge_w[m * 128 + j] * We[l * 16384 + j * 128 + h * 32 + c];
        g_Y[t] = acc * scale;
    } else if (t < 3072) {                // yb[l][h][c]
        int i = t - 2560;
        int l = i / 128, h = (i % 128) / 32, c = i % 32;
        float acc = 0.f;
        for (int j = 0; j < 128; j++)
            acc += edge_b[j] * We[l * 16384 + j * 128 + h * 32 + c];
        g_yb[i] = acc * scale;
    } else if (t < 5632) {                // Z2[l][m][col]
        int i = t - 3072;
        int l = i / 640, m = (i % 640) / 128, col = i % 128;
        float acc = 0.f;
        for (int j = 0; j < 128; j++)
            acc += edge_w[m * 128 + j] * We[l * 16384 + j * 128 + col];
        g_Z2[i] = acc;
    } else if (t < 6144) {                // zb2[l][col]
        int i = t - 5632;
        int l = i / 128, col = i % 128;
        float acc = 0.f;
        for (int j = 0; j < 128; j++)
            acc += edge_b[j] * We[l * 16384 + j * 128 + col];
        g_zb2[i] = acc;
    }
}

// ---------------- fused 4-matrix GEMM (proven scalar version) ----------------
#define BM 64
#define BK 16

__global__ void gemm4(const float* __restrict__ A,
                      const float* __restrict__ B0, const float* __restrict__ B1,
                      const float* __restrict__ B2, const float* __restrict__ B3,
                      const float* __restrict__ c0, const float* __restrict__ c1,
                      const float* __restrict__ c2, const float* __restrict__ c3,
                      float* __restrict__ C0, float* __restrict__ C1,
                      float* __restrict__ C2, float* __restrict__ C3)
{
    const float* B    = (blockIdx.y == 0) ? B0 : (blockIdx.y == 1) ? B1 : (blockIdx.y == 2) ? B2 : B3;
    const float* bias = (blockIdx.y == 0) ? c0 : (blockIdx.y == 1) ? c1 : (blockIdx.y == 2) ? c2 : c3;
    float* C          = (blockIdx.y == 0) ? C0 : (blockIdx.y == 1) ? C1 : (blockIdx.y == 2) ? C2 : C3;

    __shared__ float As[BK][BM + 4];
    __shared__ float Bs[BK][128];
    int tid  = threadIdx.x;
    int tcol = tid & 15;
    int trow = tid >> 4;
    int block_m = blockIdx.x * BM;

    float acc[8][8];
#pragma unroll
    for (int i = 0; i < 8; i++)
#pragma unroll
        for (int j = 0; j < 8; j++) acc[i][j] = 0.f;

    for (int k0 = 0; k0 < 128; k0 += BK) {
#pragma unroll
        for (int it = 0; it < 2; it++) {
            int f = tid + it * 128;
            int row = f >> 2;
            int kq  = f & 3;
            float4 a = *(const float4*)&A[(size_t)(block_m + row) * 128 + k0 + kq * 4];
            As[kq * 4 + 0][row] = a.x;
            As[kq * 4 + 1][row] = a.y;
            As[kq * 4 + 2][row] = a.z;
            As[kq * 4 + 3][row] = a.w;
        }
#pragma unroll
        for (int it = 0; it < 4; it++) {
            int f = tid + it * 128;
            int krow = f >> 5;
            int nq   = f & 31;
            *(float4*)&Bs[krow][nq * 4] = *(const float4*)&B[(k0 + krow) * 128 + nq * 4];
        }
        __syncthreads();
#pragma unroll
        for (int k = 0; k < BK; k++) {
            float a[8], b[8];
            *(float4*)&a[0] = *(float4*)&As[k][trow * 4];
            *(float4*)&a[4] = *(float4*)&As[k][32 + trow * 4];
            *(float4*)&b[0] = *(float4*)&Bs[k][tcol * 4];
            *(float4*)&b[4] = *(float4*)&Bs[k][64 + tcol * 4];
#pragma unroll
            for (int i = 0; i < 8; i++)
#pragma unroll
                for (int j = 0; j < 8; j++)
                    acc[i][j] += a[i] * b[j];
        }
        __syncthreads();
    }

    float4 bLo = *(const float4*)&bias[tcol * 4];
    float4 bHi = *(const float4*)&bias[64 + tcol * 4];
#pragma unroll
    for (int i = 0; i < 8; i++) {
        int row = block_m + ((i < 4) ? (trow * 4 + i) : (32 + trow * 4 + i - 4));
        float4 lo, hi;
        lo.x = acc[i][0] + bLo.x; lo.y = acc[i][1] + bLo.y;
        lo.z = acc[i][2] + bLo.z; lo.w = acc[i][3] + bLo.w;
        hi.x = acc[i][4] + bHi.x; hi.y = acc[i][5] + bHi.y;
        hi.z = acc[i][6] + bHi.z; hi.w = acc[i][7] + bHi.w;
        *(float4*)&C[(size_t)row * 128 + tcol * 4]      = lo;
        *(float4*)&C[(size_t)row * 128 + 64 + tcol * 4] = hi;
    }
}

// ---------------- attention v9: fully fused (z prologue + edges + og + LN + ReLU) --------
__global__ void k_attn6(const float* __restrict__ q, const float* __restrict__ kk,
                        const float* __restrict__ vv, const float* __restrict__ sk,
                        const float* __restrict__ lng, const float* __restrict__ lnb,
                        int l, float* __restrict__ hout)
{
    int wrp  = (blockIdx.x * blockDim.x + threadIdx.x) >> 5;
    int lane = threadIdx.x & 31;
    if (wrp >= NN) return;
    int g  = lane >> 3;
    int l8 = lane & 7;
    const float scale = 0.17677669529663687f;
    const unsigned FULL = 0xffffffffu;

    // raw q chunk for own head
    float4 qr = *(const float4*)(q + (size_t)wrp * 128 + g * 32 + l8 * 4);

    // ---- z prologue ----
    const float* Yh  = g_Y  + (size_t)(l * 4 + g) * 160 + l8 * 4;
    const float* ybh = g_yb + (size_t)(l * 4 + g) * 32  + l8 * 4;
    float4 y0 = *(const float4*)(Yh +   0);
    float4 y1 = *(const float4*)(Yh +  32);
    float4 y2 = *(const float4*)(Yh +  64);
    float4 y3 = *(const float4*)(Yh +  96);
    float4 y4 = *(const float4*)(Yh + 128);
    float4 yB = *(const float4*)(ybh);
    float z0 = qr.x * y0.x + qr.y * y0.y + qr.z * y0.z + qr.w * y0.w;
    float z1 = qr.x * y1.x + qr.y * y1.y + qr.z * y1.z + qr.w * y1.w;
    float z2 = qr.x * y2.x + qr.y * y2.y + qr.z * y2.z + qr.w * y2.w;
    float z3 = qr.x * y3.x + qr.y * y3.y + qr.z * y3.z + qr.w * y3.w;
    float z4 = qr.x * y4.x + qr.y * y4.y + qr.z * y4.z + qr.w * y4.w;
    float zb = qr.x * yB.x + qr.y * yB.y + qr.z * yB.z + qr.w * yB.w;
#pragma unroll
    for (int off = 1; off < 8; off <<= 1) {
        z0 += __shfl_xor_sync(FULL, z0, off);
        z1 += __shfl_xor_sync(FULL, z1, off);
        z2 += __shfl_xor_sync(FULL, z2, off);
        z3 += __shfl_xor_sync(FULL, z3, off);
        z4 += __shfl_xor_sync(FULL, z4, off);
        zb += __shfl_xor_sync(FULL, zb, off);
    }

    float4 q4;
    q4.x = qr.x * scale; q4.y = qr.y * scale;
    q4.z = qr.z * scale; q4.w = qr.w * scale;

    float ssum = 0.f;
    float ag0 = 0.f, ag1 = 0.f, ag2 = 0.f, ag3 = 0.f, ag4 = 0.f;
    float4 vacc = make_float4(0.f, 0.f, 0.f, 0.f);

    int beg = g_rowstart[wrp], end = g_rowstart[wrp + 1];
    int idx = beg;

    for (; idx + 1 < end; idx += 2) {
        int sA = g_csrsrc[idx];
        int sB = g_csrsrc[idx + 1];
        float4 eaA  = *(const float4*)(g_eap + (size_t)idx * 8);
        float  eaA4 = g_eap[(size_t)idx * 8 + 4];
        float4 eaB  = *(const float4*)(g_eap + (size_t)(idx + 1) * 8);
        float  eaB4 = g_eap[(size_t)(idx + 1) * 8 + 4];
        float4 kA = *(const float4*)(kk + (size_t)sA * 128 + g * 32 + l8 * 4);
        float4 kB = *(const float4*)(kk + (size_t)sB * 128 + g * 32 + l8 * 4);
        float4 vA = *(const float4*)(vv + (size_t)sA * 128 + g * 32 + l8 * 4);
        float4 vB = *(const float4*)(vv + (size_t)sB * 128 + g * 32 + l8 * 4);

        float pA = q4.x * kA.x + q4.y * kA.y + q4.z * kA.z + q4.w * kA.w;
        float pB = q4.x * kB.x + q4.y * kB.y + q4.z * kB.z + q4.w * kB.w;
        pA += __shfl_xor_sync(FULL, pA, 1);  pB += __shfl_xor_sync(FULL, pB, 1);
        pA += __shfl_xor_sync(FULL, pA, 2);  pB += __shfl_xor_sync(FULL, pB, 2);
        pA += __shfl_xor_sync(FULL, pA, 4);  pB += __shfl_xor_sync(FULL, pB, 4);

        float dA = zb + eaA.x * z0 + eaA.y * z1 + eaA.z * z2 + eaA.w * z3 + eaA4 * z4;
        float dB = zb + eaB.x * z0 + eaB.y * z1 + eaB.z * z2 + eaB.w * z3 + eaB4 * z4;

        float wA = __expf(pA + dA);
        float wB = __expf(pB + dB);
        ssum += wA + wB;

        ag0 += wA * eaA.x + wB * eaB.x;
        ag1 += wA * eaA.y + wB * eaB.y;
        ag2 += wA * eaA.z + wB * eaB.z;
        ag3 += wA * eaA.w + wB * eaB.w;
        ag4 += wA * eaA4  + wB * eaB4;

        vacc.x += wA * vA.x + wB * vB.x;
        vacc.y += wA * vA.y + wB * vB.y;
        vacc.z += wA * vA.z + wB * vB.z;
        vacc.w += wA * vA.w + wB * vB.w;
    }

    if (idx < end) {
        int sA = g_csrsrc[idx];
        float4 eaA  = *(const float4*)(g_eap + (size_t)idx * 8);
        float  eaA4 = g_eap[(size_t)idx * 8 + 4];
        float4 kA = *(const float4*)(kk + (size_t)sA * 128 + g * 32 + l8 * 4);
        float4 vA = *(const float4*)(vv + (size_t)sA * 128 + g * 32 + l8 * 4);

        float pA = q4.x * kA.x + q4.y * kA.y + q4.z * kA.z + q4.w * kA.w;
        pA += __shfl_xor_sync(FULL, pA, 1);
        pA += __shfl_xor_sync(FULL, pA, 2);
        pA += __shfl_xor_sync(FULL, pA, 4);

        float dA = zb + eaA.x * z0 + eaA.y * z1 + eaA.z * z2 + eaA.w * z3 + eaA4 * z4;
        float wA = __expf(pA + dA);
        ssum += wA;
        ag0 += wA * eaA.x; ag1 += wA * eaA.y; ag2 += wA * eaA.z;
        ag3 += wA * eaA.w; ag4 += wA * eaA4;
        vacc.x += wA * vA.x; vacc.y += wA * vA.y;
        vacc.z += wA * vA.z; vacc.w += wA * vA.w;
    }

    float inv = 1.f / (ssum + 1e-16f);

    // ---- fused epilogue: tmpv + og + LN + ReLU (all in registers) ----
    // a0..a4, mass are group-uniform = exactly this head's aggregates
    float a0 = ag0 * inv, a1 = ag1 * inv, a2 = ag2 * inv;
    float a3 = ag3 * inv, a4 = ag4 * inv;
    float mass = ssum * inv;

    const float* Z2l  = g_Z2  + (size_t)l * 640;
    const float* zb2l = g_zb2 + (size_t)l * 128;
    float4 w0 = *(const float4*)&Z2l[  0 + lane * 4];
    float4 w1 = *(const float4*)&Z2l[128 + lane * 4];
    float4 w2 = *(const float4*)&Z2l[256 + lane * 4];
    float4 w3 = *(const float4*)&Z2l[384 + lane * 4];
    float4 w4 = *(const float4*)&Z2l[512 + lane * 4];
    float4 zc = *(const float4*)&zb2l[lane * 4];

    float4 s4 = *(const float4*)(sk + (size_t)wrp * 128 + lane * 4);
    float ox = vacc.x * inv + s4.x + a0 * w0.x + a1 * w1.x + a2 * w2.x + a3 * w3.x + a4 * w4.x + mass * zc.x;
    float oy = vacc.y * inv + s4.y + a0 * w0.y + a1 * w1.y + a2 * w2.y + a3 * w3.y + a4 * w4.y + mass * zc.y;
    float oz = vacc.z * inv + s4.z + a0 * w0.z + a1 * w1.z + a2 * w2.z + a3 * w3.z + a4 * w4.z + mass * zc.z;
    float ow = vacc.w * inv + s4.w + a0 * w0.w + a1 * w1.w + a2 * w2.w + a3 * w3.w + a4 * w4.w + mass * zc.w;

    float s = ox + oy + oz + ow;
#pragma unroll
    for (int off = 16; off; off >>= 1) s += __shfl_xor_sync(FULL, s, off);
    float mu = s * 0.0078125f;
    float dx = ox - mu, dy = oy - mu, dz = oz - mu, dw = ow - mu;
    float sq = dx * dx + dy * dy + dz * dz + dw * dw;
#pragma unroll
    for (int off = 16; off; off >>= 1) sq += __shfl_xor_sync(FULL, sq, off);
    float r = rsqrtf(sq * 0.0078125f + 1e-5f);

    float4 g4 = *(const float4*)&lng[lane * 4];
    float4 b4 = *(const float4*)&lnb[lane * 4];
    float4 res;
    res.x = fmaxf(0.f, dx * r * g4.x + b4.x);
    res.y = fmaxf(0.f, dy * r * g4.y + b4.y);
    res.z = fmaxf(0.f, dz * r * g4.z + b4.z);
    res.w = fmaxf(0.f, dw * r * g4.w + b4.w);
    *(float4*)(hout + (size_t)wrp * 128 + lane * 4) = res;
}

// ---------------- global mean pool + MLP heads ----------------
__global__ void k_pool(const float* __restrict__ h, const int* __restrict__ batch)
{
    int t = blockIdx.x * blockDim.x + threadIdx.x;
    if (t >= NN * HH) return;
    int n = t >> 7, c = t & 127;
    int b = batch[n];
    atomicAdd(&g_pool[b * HH + c], h[t]);
    if (c == 0) atomicAdd(&g_pcnt[b], 1.f);
}

__global__ void k_heads(const float* __restrict__ dw1, const float* __restrict__ db1,
                        const float* __restrict__ dw2, const float* __restrict__ db2,
                        const float* __restrict__ tw1, const float* __restrict__ tb1,
                        const float* __restrict__ tw2, const float* __restrict__ tb2,
                        float* __restrict__ out)
{
    const float* W1 = blockIdx.x ? tw1 : dw1;
    const float* B1 = blockIdx.x ? tb1 : db1;
    const float* W2 = blockIdx.x ? tw2 : dw2;
    const float* B2 = blockIdx.x ? tb2 : db2;

    __shared__ float hg[GG][HH];
    __shared__ float t1[GG][64];
    int t = threadIdx.x;

    for (int i = t; i < GG * HH; i += 256) {
        int g = i >> 7;
        hg[g][i & 127] = g_pool[i] / fmaxf(g_pcnt[g], 1.f);
    }
    __syncthreads();
    for (int i = t; i < GG * 64; i += 256) {
        int g = i >> 6, j = i & 63;
        float acc = B1[j];
        for (int c = 0; c < 128; c++) acc += hg[g][c] * W1[c * 64 + j];
        t1[g][j] = fmaxf(acc, 0.f);
    }
    __syncthreads();
    for (int i = t; i < GG * OO; i += 256) {
        int g = i / OO, o = i % OO;
        float acc = B2[o];
        for (int j = 0; j < 64; j++) acc += t1[g][j] * W2[j * OO + o];
        out[blockIdx.x * GG * OO + i] = acc;
    }
}

// ---------------- launch ----------------
extern "C" void kernel_launch(void* const* d_in, const int* in_sizes, int n_in,
                              void* d_out, int out_size)
{
    const float* x      = (const float*)d_in[0];
    const float* eattr  = (const float*)d_in[1];
    const float* node_w = (const float*)d_in[2];
    const float* node_b = (const float*)d_in[3];
    const float* edge_w = (const float*)d_in[4];
    const float* edge_b = (const float*)d_in[5];
    const float* Wq  = (const float*)d_in[6];
    const float* bq  = (const float*)d_in[7];
    const float* Wk  = (const float*)d_in[8];
    const float* bk  = (const float*)d_in[9];
    const float* Wv  = (const float*)d_in[10];
    const float* bv  = (const float*)d_in[11];
    const float* We  = (const float*)d_in[12];
    const float* Wsk = (const float*)d_in[13];
    const float* bsk = (const float*)d_in[14];
    const float* lng = (const float*)d_in[15];
    const float* lnb = (const float*)d_in[16];
    const float* dw1 = (const float*)d_in[17];
    const float* db1 = (const float*)d_in[18];
    const float* dw2 = (const float*)d_in[19];
    const float* db2 = (const float*)d_in[20];
    const float* tw1 = (const float*)d_in[21];
    const float* tb1 = (const float*)d_in[22];
    const float* tw2 = (const float*)d_in[23];
    const float* tb2 = (const float*)d_in[24];
    const int*   ei    = (const int*)d_in[25];
    const int*   batch = (const int*)d_in[26];
    float* out = (float*)d_out;

    float *hA, *hB, *qp, *kp, *vp, *sp;
    cudaGetSymbolAddress((void**)&hA, g_hA);
    cudaGetSymbolAddress((void**)&hB, g_hB);
    cudaGetSymbolAddress((void**)&qp, g_q);
    cudaGetSymbolAddress((void**)&kp, g_k);
    cudaGetSymbolAddress((void**)&vp, g_v);
    cudaGetSymbolAddress((void**)&sp, g_s);

    dim3 gg(NN / BM, 4);

    // gemm4 (layer 0) stays in the ncu-profiled slot (#4).
    k_zero<<<(NN + 255) / 256, 256>>>();
    k_hist<<<(EE + 255) / 256, 256>>>(ei);
    k_nodeproj<<<(NN * HH + 255) / 256, 256>>>(x, node_w, node_b);
    gemm4<<<gg, 128>>>(hA, Wq, Wk, Wv, Wsk, bq, bk, bv, bsk, qp, kp, vp, sp);
    k_scan<<<1, 1024>>>();
    k_scatter<<<(EE + 255) / 256, 256>>>(ei);
    k_permea<<<(EE + 255) / 256, 256>>>(eattr);
    k_prep<<<24, 256>>>(We, edge_w, edge_b);

    float* hcur = hA;
    float* hnxt = hB;
    for (int i = 0; i < LL; i++) {
        if (i > 0)
            gemm4<<<gg, 128>>>(hcur,
                               Wq + i * HH * HH, Wk + i * HH * HH,
                               Wv + i * HH * HH, Wsk + i * HH * HH,
                               bq + i * HH, bk + i * HH, bv + i * HH, bsk + i * HH,
                               qp, kp, vp, sp);
        k_attn6<<<(NN * 32) / 256, 256>>>(qp, kp, vp, sp,
                                          lng + i * HH, lnb + i * HH, i, hnxt);
        float* tmp = hcur; hcur = hnxt; hnxt = tmp;
    }

    k_pool<<<(NN * HH + 255) / 256, 256>>>(hcur, batch);
    k_heads<<<2, 256>>>(dw1, db1, dw2, db2, tw1, tb1, tw2, tb2, out);
}